// round 13
// baseline (speedup 1.0000x reference)
#include <cuda_runtime.h>
#include <cstdint>

// MultiIndexSelect: out[to_k[i]] = mat_k[from_k[i]], k=0..2, L=400000, D=64 f32.
// Evidence: traffic is compulsory (~530MB) and DRAM eff pinned ~66% by RANDOM
// 256B reads (R12: seq writes didn't help -> reads are the loss). Strategy:
// bucket entries by (mat, src>>7) so the gather sweeps each matrix in ascending
// source order (dense DRAM pages, adjacent dups -> L1/L2 hits). Preprocessing
// (hist + scan + scatter over <=10MB, L2-resident) costs ~10us.

static constexpr int MAXN  = 1200000;   // 3*L
static constexpr int SHIFT = 7;         // 128 rows = 32KB source window/bucket
static constexpr int NBK   = 4096;      // buckets per matrix (500k>>7 < 4096)
static constexpr int NB    = 3 * NBK;   // 12288 = 256*48

__device__ int   g_hist[NB];
__device__ int   g_off[NB];
__device__ uint2 g_pairs[MAXN];         // x = src, y = dst | (k<<28)

__global__ __launch_bounds__(256) void zero_hist_kernel() {
    int i = blockIdx.x * blockDim.x + threadIdx.x;
    if (i < NB) g_hist[i] = 0;
}

__global__ __launch_bounds__(256) void hist_kernel(
    const int* __restrict__ f0, const int* __restrict__ f1,
    const int* __restrict__ f2, int L)
{
    int j = blockIdx.x * blockDim.x + threadIdx.x;
    if (j >= 3 * L) return;
    int k, src;
    if (j < L)          { k = 0; src = __ldg(&f0[j]); }
    else if (j < 2 * L) { k = 1; src = __ldg(&f1[j - L]); }
    else                { k = 2; src = __ldg(&f2[j - 2 * L]); }
    atomicAdd(&g_hist[k * NBK + (src >> SHIFT)], 1);
}

// Exclusive prefix over NB=12288 counters. One block, 256 threads x 48 elems.
__global__ __launch_bounds__(256) void scan_kernel() {
    __shared__ int part[256];
    int t = threadIdx.x;
    int base = t * 48;
    int loc[48];
    int s = 0;
    #pragma unroll
    for (int i = 0; i < 48; i++) { loc[i] = s; s += g_hist[base + i]; }
    part[t] = s;
    __syncthreads();
    for (int d = 1; d < 256; d <<= 1) {
        int v = (t >= d) ? part[t - d] : 0;
        __syncthreads();
        part[t] += v;
        __syncthreads();
    }
    int prev = (t == 0) ? 0 : part[t - 1];
    #pragma unroll
    for (int i = 0; i < 48; i++) g_off[base + i] = prev + loc[i];
}

__global__ __launch_bounds__(256) void scatter_kernel(
    const int* __restrict__ f0, const int* __restrict__ f1,
    const int* __restrict__ f2,
    const int* __restrict__ t0, const int* __restrict__ t1,
    const int* __restrict__ t2, int L)
{
    int j = blockIdx.x * blockDim.x + threadIdx.x;
    if (j >= 3 * L) return;
    int k, src, dst;
    if (j < L)          { k = 0; src = __ldg(&f0[j]);        dst = __ldg(&t0[j]); }
    else if (j < 2 * L) { k = 1; src = __ldg(&f1[j - L]);    dst = __ldg(&t1[j - L]); }
    else                { k = 2; src = __ldg(&f2[j - 2*L]);  dst = __ldg(&t2[j - 2*L]); }
    int p = atomicAdd(&g_off[k * NBK + (src >> SHIFT)], 1);
    g_pairs[p] = make_uint2((unsigned)src, (unsigned)dst | ((unsigned)k << 28u));
}

static constexpr int UNROLL = 4;

__global__ __launch_bounds__(256) void gather_sorted_kernel(
    const float4* __restrict__ m0,
    const float4* __restrict__ m1,
    const float4* __restrict__ m2,
    float4* __restrict__ out, int L)
{
    const unsigned total = 3u * (unsigned)L * 16u;     // 19.2M float4 slots
    const unsigned base  = blockIdx.x * (256u * UNROLL) + threadIdx.x;

    float4   val[UNROLL];
    unsigned os[UNROLL];
    bool     ok[UNROLL];

    #pragma unroll
    for (int u = 0; u < UNROLL; u++) {
        unsigned tid = base + u * 256u;
        ok[u] = (tid < total);
        if (ok[u]) {
            unsigned p    = tid >> 4;                  // sorted entry index
            unsigned lane = tid & 15u;
            uint2 e = __ldg(&g_pairs[p]);              // sequential, bcast x16
            unsigned k   = e.y >> 28u;
            unsigned dst = e.y & 0x0FFFFFFFu;
            unsigned src = e.x;
            const float4* __restrict__ mat = (k == 0) ? m0 : (k == 1) ? m1 : m2;
            os[u]  = dst * 16u + lane;
            val[u] = __ldcs(&mat[(size_t)src * 16u + lane]);   // ascending src order
        }
    }
    #pragma unroll
    for (int u = 0; u < UNROLL; u++) {
        if (ok[u]) __stcs(&out[os[u]], val[u]);
    }
}

extern "C" void kernel_launch(void* const* d_in, const int* in_sizes, int n_in,
                              void* d_out, int out_size)
{
    const float4* m0 = (const float4*)d_in[0];
    const float4* m1 = (const float4*)d_in[1];
    const float4* m2 = (const float4*)d_in[2];
    const int* f0 = (const int*)d_in[3];
    const int* f1 = (const int*)d_in[4];
    const int* f2 = (const int*)d_in[5];
    const int* t0 = (const int*)d_in[6];
    const int* t1 = (const int*)d_in[7];
    const int* t2 = (const int*)d_in[8];

    int L = in_sizes[3];                               // 400000
    int n  = 3 * L;

    zero_hist_kernel<<<(NB + 255) / 256, 256>>>();
    hist_kernel<<<(n + 255) / 256, 256>>>(f0, f1, f2, L);
    scan_kernel<<<1, 256>>>();
    scatter_kernel<<<(n + 255) / 256, 256>>>(f0, f1, f2, t0, t1, t2, L);

    unsigned total = 3u * (unsigned)L * 16u;
    unsigned per_block = 256u * UNROLL;
    unsigned blocks = (total + per_block - 1) / per_block;
    gather_sorted_kernel<<<blocks, 256>>>(m0, m1, m2, (float4*)d_out, L);
}

// round 15
// speedup vs baseline: 1.7040x; 1.7040x over previous
#include <cuda_runtime.h>
#include <cstdint>

// MultiIndexSelect: out[to_k[i]] = mat_k[from_k[i]], k=0..2, L=400000, D=64 f32.
// Row = 256 B = 16 float4 slots. Evidence: perf tracks occ x MLP (R4 3.3->96.5us,
// R10 5.2->94.75us). cp.async gathers keep outstanding loads out of the register
// file; THREADS=128 + UNROLL=8 gives 16KB smem/block -> 14 blocks/SM (87.5% occ)
// with 8 gathers in flight per thread (product 7.0). Single commit group/wait.
// 19.2M slots / 1024 = 18750 blocks exactly -> branchless fast path.

static constexpr int UNROLL  = 8;
static constexpr int THREADS = 128;

__global__ __launch_bounds__(THREADS) void multi_index_select_kernel(
    const float4* __restrict__ m0,
    const float4* __restrict__ m1,
    const float4* __restrict__ m2,
    const int* __restrict__ f0,
    const int* __restrict__ f1,
    const int* __restrict__ f2,
    const int* __restrict__ t0,
    const int* __restrict__ t1,
    const int* __restrict__ t2,
    float4* __restrict__ out,
    int L)
{
    __shared__ float4 buf[THREADS * UNROLL];            // 16 KB, private slot per (thread,u)

    const unsigned total = 3u * (unsigned)L * 16u;      // 19.2M slots
    const unsigned base  = blockIdx.x * (THREADS * UNROLL) + threadIdx.x;

    const unsigned smem_base =
        (unsigned)__cvta_generic_to_shared(buf) + threadIdx.x * 16u;

    unsigned dslot[UNROLL];

    if (base + (UNROLL - 1) * THREADS < total) {
        // Fast path (every block for L=400000): branchless, all 16 index loads
        // + 8 register-free gathers issued back-to-back, one commit group.
        #pragma unroll
        for (int u = 0; u < UNROLL; u++) {
            unsigned tid  = base + u * THREADS;
            unsigned row  = tid >> 4;
            unsigned lane = tid & 15u;
            const float4* __restrict__ mat;
            int src, dst;
            if (row < (unsigned)L) {
                mat = m0; src = __ldg(&f0[row]);        dst = __ldg(&t0[row]);
            } else if (row < 2u * (unsigned)L) {
                unsigned r = row - (unsigned)L;
                mat = m1; src = __ldg(&f1[r]);          dst = __ldg(&t1[r]);
            } else {
                unsigned r = row - 2u * (unsigned)L;
                mat = m2; src = __ldg(&f2[r]);          dst = __ldg(&t2[r]);
            }
            dslot[u] = (unsigned)dst * 16u + lane;
            const float4* gsrc = &mat[(size_t)src * 16u + lane];
            unsigned saddr = smem_base + (unsigned)(u * THREADS) * 16u;
            asm volatile("cp.async.cg.shared.global [%0], [%1], 16;\n"
                         :: "r"(saddr), "l"(gsrc) : "memory");
        }
        asm volatile("cp.async.commit_group;\n" ::: "memory");
        asm volatile("cp.async.wait_group 0;\n"  ::: "memory");

        #pragma unroll
        for (int u = 0; u < UNROLL; u++) {
            float4 v = buf[u * THREADS + threadIdx.x];
            __stcs(&out[dslot[u]], v);
        }
    } else {
        // Generic tail (unused for L=400000).
        #pragma unroll
        for (int u = 0; u < UNROLL; u++) {
            unsigned tid = base + u * THREADS;
            if (tid >= total) continue;
            unsigned row  = tid >> 4;
            unsigned lane = tid & 15u;
            const float4* __restrict__ mat;
            int src, dst;
            if (row < (unsigned)L) {
                mat = m0; src = __ldg(&f0[row]);        dst = __ldg(&t0[row]);
            } else if (row < 2u * (unsigned)L) {
                unsigned r = row - (unsigned)L;
                mat = m1; src = __ldg(&f1[r]);          dst = __ldg(&t1[r]);
            } else {
                unsigned r = row - 2u * (unsigned)L;
                mat = m2; src = __ldg(&f2[r]);          dst = __ldg(&t2[r]);
            }
            __stcs(&out[(size_t)dst * 16u + lane],
                   __ldcs(&mat[(size_t)src * 16u + lane]));
        }
    }
}

extern "C" void kernel_launch(void* const* d_in, const int* in_sizes, int n_in,
                              void* d_out, int out_size)
{
    const float4* m0 = (const float4*)d_in[0];
    const float4* m1 = (const float4*)d_in[1];
    const float4* m2 = (const float4*)d_in[2];
    const int* f0 = (const int*)d_in[3];
    const int* f1 = (const int*)d_in[4];
    const int* f2 = (const int*)d_in[5];
    const int* t0 = (const int*)d_in[6];
    const int* t1 = (const int*)d_in[7];
    const int* t2 = (const int*)d_in[8];

    int L = in_sizes[3];                                 // 400000
    unsigned total = 3u * (unsigned)L * 16u;
    unsigned per_block = THREADS * UNROLL;               // 1024
    unsigned blocks = (total + per_block - 1) / per_block;   // 18750 exact

    multi_index_select_kernel<<<blocks, THREADS>>>(
        m0, m1, m2, f0, f1, f2, t0, t1, t2, (float4*)d_out, L);
}